// round 1
// baseline (speedup 1.0000x reference)
#include <cuda_runtime.h>
#include <cuda_bf16.h>

// 3x3 erosion (min) + dilation (max), replicate-border (== +/-inf padding for
// min/max), on NCHW fp32 with H=W=512. Output: [dilated | eroded] concatenated.

constexpr int W    = 512;   // row width (fixed by problem)
constexpr int H    = 512;   // plane height
constexpr int TPB  = 128;   // threads/block; each thread owns 4 contiguous cols
constexpr int ROWS = 128;   // output rows per block

__global__ __launch_bounds__(TPB)
void morph3x3_kernel(const float* __restrict__ x,
                     float* __restrict__ dil,
                     float* __restrict__ ero)
{
    __shared__ float buf[2][W];

    const int plane = blockIdx.y;
    const int r0    = blockIdx.x * ROWS;
    const size_t pbase = (size_t)plane * H * W;
    const float* __restrict__ xp = x   + pbase;
    float* __restrict__ dp       = dil + pbase;
    float* __restrict__ ep       = ero + pbase;

    const int c = threadIdx.x * 4;

    // rolling horizontal results: [0]=newest row, [2]=oldest
    float4 hx0, hx1, hx2;   // horizontal max
    float4 hn0, hn1, hn2;   // horizontal min

    // prefetch first row (ir = r0-1, clamped)
    int ir_first = r0 - 1; if (ir_first < 0) ir_first = 0;
    float4 v_next = *reinterpret_cast<const float4*>(xp + (size_t)ir_first * W + c);

    int p = 0;
    #pragma unroll 2
    for (int ir = r0 - 1; ir <= r0 + ROWS; ++ir, p ^= 1) {
        float4 v = v_next;

        // issue next row's load early (overlaps barrier + compute below)
        if (ir < r0 + ROWS) {
            int nxt = ir + 1;
            if (nxt >= H) nxt = H - 1;
            v_next = *reinterpret_cast<const float4*>(xp + (size_t)nxt * W + c);
        }

        *reinterpret_cast<float4*>(&buf[p][c]) = v;
        __syncthreads();

        const float lf = buf[p][c == 0 ? 0 : c - 1];
        const float rt = buf[p][c + 4 >= W ? W - 1 : c + 4];

        // horizontal 3-tap max/min (clamp-to-edge replication)
        float4 hx, hn;
        hx.x = fmaxf(fmaxf(lf,  v.x), v.y);
        hx.y = fmaxf(fmaxf(v.x, v.y), v.z);
        hx.z = fmaxf(fmaxf(v.y, v.z), v.w);
        hx.w = fmaxf(fmaxf(v.z, v.w), rt);
        hn.x = fminf(fminf(lf,  v.x), v.y);
        hn.y = fminf(fminf(v.x, v.y), v.z);
        hn.z = fminf(fminf(v.y, v.z), v.w);
        hn.w = fminf(fminf(v.z, v.w), rt);

        // roll vertical window
        hx2 = hx1; hx1 = hx0; hx0 = hx;
        hn2 = hn1; hn1 = hn0; hn0 = hn;

        const int oy = ir - 1;
        if (oy >= r0 && oy < r0 + ROWS) {
            float4 dmax, dmin;
            dmax.x = fmaxf(fmaxf(hx2.x, hx1.x), hx0.x);
            dmax.y = fmaxf(fmaxf(hx2.y, hx1.y), hx0.y);
            dmax.z = fmaxf(fmaxf(hx2.z, hx1.z), hx0.z);
            dmax.w = fmaxf(fmaxf(hx2.w, hx1.w), hx0.w);
            dmin.x = fminf(fminf(hn2.x, hn1.x), hn0.x);
            dmin.y = fminf(fminf(hn2.y, hn1.y), hn0.y);
            dmin.z = fminf(fminf(hn2.z, hn1.z), hn0.z);
            dmin.w = fminf(fminf(hn2.w, hn1.w), hn0.w);
            *reinterpret_cast<float4*>(dp + (size_t)oy * W + c) = dmax;
            *reinterpret_cast<float4*>(ep + (size_t)oy * W + c) = dmin;
        }
    }
}

extern "C" void kernel_launch(void* const* d_in, const int* in_sizes, int n_in,
                              void* d_out, int out_size)
{
    const float* x = (const float*)d_in[0];
    const int n = in_sizes[0];                 // total input elements
    const int nplanes = n / (H * W);           // 8*32 = 256

    float* dil = (float*)d_out;
    float* ero = dil + (size_t)n;              // out_size == 2*n

    dim3 grid(H / ROWS, nplanes);              // (4, 256) = 1024 blocks
    morph3x3_kernel<<<grid, TPB>>>(x, dil, ero);
}